// round 1
// baseline (speedup 1.0000x reference)
#include <cuda_runtime.h>
#include <cuda_bf16.h>

// Problem dims (fixed by the dataset)
#define B  512
#define T  1024
#define IN 128
#define H  256

// ---------------- scratch (device globals: no allocation allowed) -------------
__device__ float g_cur1[(size_t)B * T * H];   // [B][T][H]  512 MB
__device__ float g_w1t[IN * H];               // [i][h]
__device__ float g_w2t[H * H];                // [j][h]  (W2 transposed)

// ---------------- prep: transpose W1 and W2 ----------------------------------
__global__ void prep_kernel(const float* __restrict__ W1, const float* __restrict__ W2) {
    int tid = blockIdx.x * blockDim.x + threadIdx.x;   // 0 .. 65535
    if (tid < H * IN) {
        int h = tid / IN, i = tid % IN;                // W1 [H][IN]
        g_w1t[i * H + h] = W1[tid];
    }
    if (tid < H * H) {
        int h = tid >> 8, j = tid & 255;               // W2 [H][H]
        g_w2t[j * H + h] = W2[tid];
    }
}

// ---------------- phase 1: cur1 = x @ W1^T + b1 -------------------------------
// C[bt][h], M = B*T = 524288, N = 256, K = 128.
// 64x64 tile, BK=32, 256 threads, 4x4 micro-tile.
#define BM 64
#define BN 64
#define BK 32

__global__ void __launch_bounds__(256) gemm_cur1(const float* __restrict__ x,
                                                 const float* __restrict__ b1) {
    __shared__ float xs[BM][BK];
    __shared__ float ws[BK][BN];

    const int bm = blockIdx.x * BM;       // bt offset
    const int bn = blockIdx.y * BN;       // h offset
    const int tid = threadIdx.x;
    const int tx = tid & 15;              // 0..15  (cols)
    const int ty = tid >> 4;              // 0..15  (rows)

    float acc[4][4] = {};

    for (int k0 = 0; k0 < IN; k0 += BK) {
        // load xs: 64 x 32 floats, 2 float4 per thread
        #pragma unroll
        for (int l = 0; l < 2; l++) {
            int idx = tid + l * 256;             // 0..511
            int r = idx >> 3, c4 = idx & 7;
            *(float4*)&xs[r][c4 * 4] =
                *(const float4*)&x[(size_t)(bm + r) * IN + k0 + c4 * 4];
        }
        // load ws (from w1t [IN][H]): 32 x 64 floats
        #pragma unroll
        for (int l = 0; l < 2; l++) {
            int idx = tid + l * 256;
            int r = idx >> 4, c4 = idx & 15;
            *(float4*)&ws[r][c4 * 4] =
                *(const float4*)&g_w1t[(size_t)(k0 + r) * H + bn + c4 * 4];
        }
        __syncthreads();

        #pragma unroll
        for (int k = 0; k < BK; k++) {
            float a0 = xs[ty * 4 + 0][k];
            float a1 = xs[ty * 4 + 1][k];
            float a2 = xs[ty * 4 + 2][k];
            float a3 = xs[ty * 4 + 3][k];
            float4 bv = *(float4*)&ws[k][tx * 4];
            acc[0][0] += a0 * bv.x; acc[0][1] += a0 * bv.y; acc[0][2] += a0 * bv.z; acc[0][3] += a0 * bv.w;
            acc[1][0] += a1 * bv.x; acc[1][1] += a1 * bv.y; acc[1][2] += a1 * bv.z; acc[1][3] += a1 * bv.w;
            acc[2][0] += a2 * bv.x; acc[2][1] += a2 * bv.y; acc[2][2] += a2 * bv.z; acc[2][3] += a2 * bv.w;
            acc[3][0] += a3 * bv.x; acc[3][1] += a3 * bv.y; acc[3][2] += a3 * bv.z; acc[3][3] += a3 * bv.w;
        }
        __syncthreads();
    }

    float4 bias = *(const float4*)&b1[bn + tx * 4];
    #pragma unroll
    for (int r = 0; r < 4; r++) {
        float4 o;
        o.x = acc[r][0] + bias.x;
        o.y = acc[r][1] + bias.y;
        o.z = acc[r][2] + bias.z;
        o.w = acc[r][3] + bias.w;
        *(float4*)&g_cur1[(size_t)(bm + ty * 4 + r) * H + bn + tx * 4] = o;
    }
}

// ---------------- phase 2: sequential scan, one CTA per batch element ---------
// 256 threads; thread t owns neuron h=t of both hidden layers.
// spk1 is binary -> cur2 is a sparse gather-sum of W2T rows (L1/L2 resident).
__global__ void __launch_bounds__(256) scan_kernel(const float* __restrict__ b2,
                                                   const float* __restrict__ wout,
                                                   const float* __restrict__ boutp,
                                                   const float* __restrict__ pb1,
                                                   const float* __restrict__ pb2,
                                                   const float* __restrict__ pbo,
                                                   float* __restrict__ out) {
    const int b    = blockIdx.x;
    const int tid  = threadIdx.x;
    const int lane = tid & 31;
    const int wid  = tid >> 5;

    const float bt1 = fminf(fmaxf(pb1[0], 0.f), 1.f);
    const float bt2 = fminf(fmaxf(pb2[0], 0.f), 1.f);
    const float bto = fminf(fmaxf(pbo[0], 0.f), 1.f);
    const float boutv = boutp[0];
    const float b2v   = b2[tid];
    const float woutv = wout[tid];

    __shared__ unsigned       bits[8];
    __shared__ unsigned short list[H];
    __shared__ float          wsum[8];

    float mem1 = 0.f, mem2 = 0.f, memo = 0.f;
    float s1p = 0.f, s2p = 0.f;

    const float* c1p  = g_cur1 + (size_t)b * T * H + tid;
    float*       outp = out + (size_t)b * T;

    // software-pipeline cur1 one step ahead (hide DRAM latency of the stream)
    float c1 = c1p[0];

    for (int t = 0; t < T; t++) {
        float c1n = (t + 1 < T) ? c1p[(size_t)(t + 1) * H] : 0.f;

        // layer 1 membrane update (reset uses previous-step spike)
        mem1 = bt1 * mem1 + c1 - s1p;
        bool s1 = mem1 > 1.0f;

        unsigned bal = __ballot_sync(0xffffffffu, s1);
        if (lane == 0) bits[wid] = bal;
        __syncthreads();

        // build compact active list (uniform across threads)
        int n = 0, myoff = 0;
        #pragma unroll
        for (int w = 0; w < 8; w++) {
            int c = __popc(bits[w]);
            if (w < wid) myoff += c;
            n += c;
        }
        if (s1) {
            int pos = myoff + __popc(bal & ((1u << lane) - 1u));
            list[pos] = (unsigned short)tid;
        }
        s1p = s1 ? 1.f : 0.f;
        __syncthreads();

        // sparse gather-sum: cur2[h] = b2[h] + sum_{active j} W2T[j][h]
        float a0 = 0.f, a1 = 0.f, a2 = 0.f, a3 = 0.f;
        int k = 0;
        for (; k + 4 <= n; k += 4) {
            int j0 = list[k + 0];
            int j1 = list[k + 1];
            int j2 = list[k + 2];
            int j3 = list[k + 3];
            a0 += g_w2t[j0 * H + tid];
            a1 += g_w2t[j1 * H + tid];
            a2 += g_w2t[j2 * H + tid];
            a3 += g_w2t[j3 * H + tid];
        }
        for (; k < n; k++) a0 += g_w2t[list[k] * H + tid];
        float cur2 = b2v + ((a0 + a1) + (a2 + a3));

        // layer 2 membrane update
        mem2 = bt2 * mem2 + cur2 - s2p;
        bool s2 = mem2 > 1.0f;
        s2p = s2 ? 1.f : 0.f;

        // readout: out = spk2 @ Wout^T + bout ; mem_out leaky-integrates
        float v = s2 ? woutv : 0.f;
        #pragma unroll
        for (int off = 16; off; off >>= 1) v += __shfl_xor_sync(0xffffffffu, v, off);
        if (lane == 0) wsum[wid] = v;
        __syncthreads();

        if (tid == 0) {
            float o = boutv;
            #pragma unroll
            for (int w = 0; w < 8; w++) o += wsum[w];
            memo = bto * memo + o;
            outp[t] = memo;
        }

        c1 = c1n;
    }
}

// ---------------- launcher ----------------------------------------------------
extern "C" void kernel_launch(void* const* d_in, const int* in_sizes, int n_in,
                              void* d_out, int out_size) {
    const float* x     = (const float*)d_in[0];   // [B,T,IN]
    const float* W1    = (const float*)d_in[1];   // [H,IN]
    const float* b1    = (const float*)d_in[2];   // [H]
    const float* W2    = (const float*)d_in[3];   // [H,H]
    const float* b2    = (const float*)d_in[4];   // [H]
    const float* Wout  = (const float*)d_in[5];   // [1,H]
    const float* bout  = (const float*)d_in[6];   // [1]
    const float* beta1 = (const float*)d_in[7];
    const float* beta2 = (const float*)d_in[8];
    const float* betao = (const float*)d_in[9];
    float* out = (float*)d_out;                   // [B,T,1]

    prep_kernel<<<(H * H + 255) / 256, 256>>>(W1, W2);

    dim3 ggrid(B * T / BM, H / BN);
    gemm_cur1<<<ggrid, 256>>>(x, b1);

    scan_kernel<<<B, 256>>>(b2, Wout, bout, beta1, beta2, betao, out);
}